// round 4
// baseline (speedup 1.0000x reference)
#include <cuda_runtime.h>
#include <cuda_bf16.h>
#include <math.h>

// Problem constants
#define Bc   4
#define Lc   16384
#define Dc   128
#define DIc  256
#define DSc  16
#define DTRc 8
#define Kc   4
#define Nc   (Bc*Lc)
#define NCH  128
#define Tc   (Lc/NCH)
#define EPSc 1e-5f

typedef unsigned int       u32;
typedef unsigned long long u64;
typedef unsigned short     u16;

// ---------------- scratch (device globals; no allocations) ----------------
__device__ float g_xi [Nc*DIc];
__device__ float g_z  [Nc*DIc];
__device__ float g_xc [Nc*DIc];
__device__ float g_dbc[Nc*40];
__device__ float g_ch [Bc*NCH*DIc*DSc];
__device__ float g_sdt[Bc*NCH*DIc];
__device__ float g_hin[Bc*NCH*DIc*DSc];
__device__ float g_y  [Nc*DIc];
// bf16 hi/lo split weights, natural [k][n] orientation
__device__ u16 g_win_hi [128*512], g_win_lo [128*512];
__device__ u16 g_wout_hi[256*128], g_wout_lo[256*128];
__device__ u16 g_wxp_hi [256*64],  g_wxp_lo [256*64];

// ---------------- helpers ----------------
__device__ __forceinline__ u32 smem_u32(const void* p) {
    u32 a;
    asm("{ .reg .u64 t; cvta.to.shared.u64 t, %1; cvt.u32.u64 %0, t; }"
        : "=r"(a) : "l"(p));
    return a;
}
__device__ __forceinline__ void bfsplit(float v, u16 &h, u16 &l) {
    __nv_bfloat16 hb = __float2bfloat16_rn(v);
    h = __bfloat16_as_ushort(hb);
    l = __bfloat16_as_ushort(__float2bfloat16_rn(v - __bfloat162float(hb)));
}
#define LDSM4(r, a) \
    asm volatile("ldmatrix.sync.aligned.m8n8.x4.shared.b16 {%0,%1,%2,%3}, [%4];" \
        : "=r"((r)[0]),"=r"((r)[1]),"=r"((r)[2]),"=r"((r)[3]) : "r"(a))
#define LDSM4T(r, a) \
    asm volatile("ldmatrix.sync.aligned.m8n8.x4.trans.shared.b16 {%0,%1,%2,%3}, [%4];" \
        : "=r"((r)[0]),"=r"((r)[1]),"=r"((r)[2]),"=r"((r)[3]) : "r"(a))
#define MMA(c, a, b) \
    asm volatile("mma.sync.aligned.m16n8k16.row.col.f32.bf16.bf16.f32 " \
        "{%0,%1,%2,%3}, {%4,%5,%6,%7}, {%8,%9}, {%0,%1,%2,%3};" \
        : "+f"((c)[0]),"+f"((c)[1]),"+f"((c)[2]),"+f"((c)[3]) \
        : "r"((a)[0]),"r"((a)[1]),"r"((a)[2]),"r"((a)[3]),"r"((b)[0]),"r"((b)[1]))

#define LDA 136   // smem row stride in bf16 (272B -> conflict-free ldmatrix)
#define LDB2 72   // x_proj B stride (144B -> conflict-free)

// =====================================================================
// K0: weight prep — bf16 hi/lo split (natural [k][n] layout, xp padded)
// =====================================================================
__global__ __launch_bounds__(256) void k_prep(
    const float* __restrict__ inw, const float* __restrict__ outw,
    const float* __restrict__ xpw)
{
    int idx = blockIdx.x*256 + threadIdx.x;
    float v; u16* dh; u16* dl; int slot;
    if (idx < 128*512) {
        v = inw[idx]; dh = g_win_hi; dl = g_win_lo; slot = idx;
    } else if (idx < 128*512 + 256*128) {
        int i = idx - 128*512;
        v = outw[i]; dh = g_wout_hi; dl = g_wout_lo; slot = i;
    } else if (idx < 128*512 + 256*128 + 256*64) {
        int i = idx - 128*512 - 256*128;
        int k = i >> 6, n = i & 63;
        v = (n < 40) ? xpw[k*40 + n] : 0.f;
        dh = g_wxp_hi; dl = g_wxp_lo; slot = i;
    } else return;
    u16 h, l; bfsplit(v, h, l);
    dh[slot] = h; dl[slot] = l;
}

// =====================================================================
// K1: fused embed + gather + RMSNorm + in_proj (HMMA, M128 blk, N=512, K=128)
// =====================================================================
__global__ __launch_bounds__(256) void k_in(
    const float* __restrict__ feats, const int* __restrict__ coords,
    const float* __restrict__ pos_w, const float* __restrict__ pos_b,
    const float* __restrict__ rms_w, const int* __restrict__ perm)
{
    extern __shared__ u16 sm[];
    u16 *Ah = sm, *Al = sm + 128*LDA, *Bh = sm + 2*128*LDA, *Bl = sm + 3*128*LDA;
    const u32 Ah_u = smem_u32(Ah), Al_u = smem_u32(Al);
    const u32 Bh_u = smem_u32(Bh), Bl_u = smem_u32(Bl);
    const int tid = threadIdx.x, lane = tid & 31, wid = tid >> 5;
    const int m0 = blockIdx.x * 128;
    const int wm = wid >> 1, wn = wid & 1;

    // prologue: gather + PE + RMSNorm -> bf16 hi/lo row-major A
    for (int r = wid; r < 128; r += 8) {
        int m   = m0 + r;
        int src = (m & ~(Lc-1)) + perm[m];
        float c0 = (float)coords[src*3+0];
        float c1 = (float)coords[src*3+1];
        float c2 = (float)coords[src*3+2];
        int c = lane*4;
        float4 f = *(const float4*)(feats + (size_t)src*Dc + c);
        float v[4]; float ss = 0.f;
        #pragma unroll
        for (int j = 0; j < 4; ++j) {
            v[j] = (&f.x)[j] + c0*pos_w[c+j] + c1*pos_w[Dc+c+j]
                   + c2*pos_w[2*Dc+c+j] + pos_b[c+j];
            ss += v[j]*v[j];
        }
        #pragma unroll
        for (int o = 16; o > 0; o >>= 1) ss += __shfl_xor_sync(0xffffffffu, ss, o);
        float rs = rsqrtf(ss*(1.f/Dc) + EPSc);
        u16 h0,l0,h1,l1,h2,l2,h3,l3;
        bfsplit(v[0]*rs*rms_w[c+0], h0, l0);
        bfsplit(v[1]*rs*rms_w[c+1], h1, l1);
        bfsplit(v[2]*rs*rms_w[c+2], h2, l2);
        bfsplit(v[3]*rs*rms_w[c+3], h3, l3);
        int base = r*LDA + c;
        *(u32*)&Ah[base]   = (u32)h0 | ((u32)h1<<16);
        *(u32*)&Ah[base+2] = (u32)h2 | ((u32)h3<<16);
        *(u32*)&Al[base]   = (u32)l0 | ((u32)l1<<16);
        *(u32*)&Al[base+2] = (u32)l2 | ((u32)l3<<16);
    }
    __syncthreads();

    for (int nb = 0; nb < 4; ++nb) {
        // load B chunk [k=128][n=128]
        for (int i = tid; i < 128*64; i += 256) {
            int k = i >> 6, p = i & 63;
            *(u32*)&Bh[k*LDA + 2*p] = ((const u32*)g_win_hi)[k*256 + nb*64 + p];
            *(u32*)&Bl[k*LDA + 2*p] = ((const u32*)g_win_lo)[k*256 + nb*64 + p];
        }
        __syncthreads();

        float acc[2][8][4] = {};
        #pragma unroll
        for (int pass = 0; pass < 3; ++pass) {
            u32 A_u = (pass == 2) ? Al_u : Ah_u;
            u32 B_u = (pass == 1) ? Bl_u : Bh_u;
            #pragma unroll
            for (int k0 = 0; k0 < 128; k0 += 16) {
                u32 a[2][4], b[8][2];
                #pragma unroll
                for (int mf = 0; mf < 2; ++mf)
                    LDSM4(a[mf], A_u + (u32)(((wm*32 + mf*16 + (lane & 15))*LDA
                                              + k0 + (lane >> 4)*8) * 2));
                #pragma unroll
                for (int nf2 = 0; nf2 < 4; ++nf2) {
                    u32 bb[4];
                    LDSM4T(bb, B_u + (u32)(((k0 + (lane & 15))*LDA
                                            + wn*64 + nf2*16 + (lane >> 4)*8) * 2));
                    b[2*nf2+0][0] = bb[0]; b[2*nf2+0][1] = bb[1];
                    b[2*nf2+1][0] = bb[2]; b[2*nf2+1][1] = bb[3];
                }
                #pragma unroll
                for (int mf = 0; mf < 2; ++mf)
                    #pragma unroll
                    for (int nf = 0; nf < 8; ++nf)
                        MMA(acc[mf][nf], a[mf], b[nf]);
            }
        }

        // store: nb 0,1 -> g_xi, nb 2,3 -> g_z
        float* dst = (nb < 2) ? g_xi : g_z;
        int nbase = (nb & 1)*128 + wn*64;
        #pragma unroll
        for (int mf = 0; mf < 2; ++mf) {
            int r0 = m0 + wm*32 + mf*16 + (lane >> 2);
            #pragma unroll
            for (int nf = 0; nf < 8; ++nf) {
                int ncol = nbase + nf*8 + (lane & 3)*2;
                *(float2*)&dst[(size_t)r0*DIc + ncol]     = make_float2(acc[mf][nf][0], acc[mf][nf][1]);
                *(float2*)&dst[(size_t)(r0+8)*DIc + ncol] = make_float2(acc[mf][nf][2], acc[mf][nf][3]);
            }
        }
        __syncthreads();
    }
}

// =====================================================================
// K2: fused conv+silu + x_proj (HMMA, M128 blk, N=64(pad of 40), K=256)
//     also writes g_xc (fp32) for the scans
// =====================================================================
__global__ __launch_bounds__(256) void k_xp(
    const float* __restrict__ cw, const float* __restrict__ cb)
{
    extern __shared__ u16 sm[];
    u16 *Ah = sm, *Al = sm + 128*LDA, *Bh = sm + 2*128*LDA, *Bl = Bh + 128*LDB2;
    const u32 Ah_u = smem_u32(Ah), Al_u = smem_u32(Al);
    const u32 Bh_u = smem_u32(Bh), Bl_u = smem_u32(Bl);
    const int tid = threadIdx.x, lane = tid & 31, wid = tid >> 5;
    const int m0 = blockIdx.x * 128;
    const int wm = wid >> 1, wn = wid & 1;

    float acc[2][4][4] = {};
    for (int kc = 0; kc < 2; ++kc) {
        int kk = kc*128;
        // A: depthwise conv + silu on the fly, write g_xc + smem bf16 hi/lo
        for (int i = tid; i < 128*64; i += 256) {
            int r = i >> 6, p = i & 63;
            int col = kk + 2*p;
            int m = m0 + r;
            float ax = cb[col], ay = cb[col+1];
            #pragma unroll
            for (int j = 0; j < Kc; ++j) {
                if (((m & (Lc-1)) - 3 + j) >= 0) {
                    float2 xv = *(const float2*)(g_xi + (size_t)(m-3+j)*DIc + col);
                    ax += xv.x * cw[col*Kc + j];
                    ay += xv.y * cw[(col+1)*Kc + j];
                }
            }
            ax = ax / (1.f + __expf(-ax));
            ay = ay / (1.f + __expf(-ay));
            *(float2*)(g_xc + (size_t)m*DIc + col) = make_float2(ax, ay);
            u16 hx,lx,hy,ly;
            bfsplit(ax,hx,lx); bfsplit(ay,hy,ly);
            int base = r*LDA + 2*p;
            *(u32*)&Ah[base] = (u32)hx | ((u32)hy<<16);
            *(u32*)&Al[base] = (u32)lx | ((u32)ly<<16);
        }
        // B chunk [k=128][n=64]
        for (int i = tid; i < 128*32; i += 256) {
            int k = i >> 5, p = i & 31;
            *(u32*)&Bh[k*LDB2 + 2*p] = ((const u32*)g_wxp_hi)[(kk+k)*32 + p];
            *(u32*)&Bl[k*LDB2 + 2*p] = ((const u32*)g_wxp_lo)[(kk+k)*32 + p];
        }
        __syncthreads();

        #pragma unroll
        for (int pass = 0; pass < 3; ++pass) {
            u32 A_u = (pass == 2) ? Al_u : Ah_u;
            u32 B_u = (pass == 1) ? Bl_u : Bh_u;
            #pragma unroll
            for (int k0 = 0; k0 < 128; k0 += 16) {
                u32 a[2][4], b[4][2];
                #pragma unroll
                for (int mf = 0; mf < 2; ++mf)
                    LDSM4(a[mf], A_u + (u32)(((wm*32 + mf*16 + (lane & 15))*LDA
                                              + k0 + (lane >> 4)*8) * 2));
                #pragma unroll
                for (int nf2 = 0; nf2 < 2; ++nf2) {
                    u32 bb[4];
                    LDSM4T(bb, B_u + (u32)(((k0 + (lane & 15))*LDB2
                                            + wn*32 + nf2*16 + (lane >> 4)*8) * 2));
                    b[2*nf2+0][0] = bb[0]; b[2*nf2+0][1] = bb[1];
                    b[2*nf2+1][0] = bb[2]; b[2*nf2+1][1] = bb[3];
                }
                #pragma unroll
                for (int mf = 0; mf < 2; ++mf)
                    #pragma unroll
                    for (int nf = 0; nf < 4; ++nf)
                        MMA(acc[mf][nf], a[mf], b[nf]);
            }
        }
        __syncthreads();
    }

    #pragma unroll
    for (int mf = 0; mf < 2; ++mf) {
        int r0 = m0 + wm*32 + mf*16 + (lane >> 2);
        #pragma unroll
        for (int nf = 0; nf < 4; ++nf) {
            int ncol = wn*32 + nf*8 + (lane & 3)*2;
            if (ncol < 40) {
                *(float2*)&g_dbc[(size_t)r0*40 + ncol]     = make_float2(acc[mf][nf][0], acc[mf][nf][1]);
                *(float2*)&g_dbc[(size_t)(r0+8)*40 + ncol] = make_float2(acc[mf][nf][2], acc[mf][nf][3]);
            }
        }
    }
}

// =====================================================================
// K3: scan pass 1 (dt inline) — per-chunk final state + sum(dt)
// =====================================================================
__global__ __launch_bounds__(256) void k_scan1(
    const float* __restrict__ A_log, const float* __restrict__ dtw,
    const float* __restrict__ dtb)
{
    __shared__ float Bsh[Tc][DSc];
    __shared__ float D8 [Tc][8];
    int blk = blockIdx.x;
    int b = blk >> 7, ch = blk & (NCH-1);
    int base = b*Lc + ch*Tc;
    int tid = threadIdx.x, lane = tid & 31, wid = tid >> 5;
    for (int t = wid; t < Tc; t += 8) {
        if (lane < 24) {
            float v = g_dbc[(size_t)(base+t)*40 + lane];
            if (lane < 8) D8[t][lane] = v; else Bsh[t][lane-8] = v;
        }
    }
    __syncthreads();
    int d = tid;
    float wr[8];
    #pragma unroll
    for (int k = 0; k < 8; ++k) wr[k] = dtw[k*DIc + d];
    float bb = dtb[d];
    float a0 = -__expf(A_log[d*DSc]);
    bool uni = true;
    #pragma unroll
    for (int s = 1; s < DSc; ++s) {
        float as = -__expf(A_log[d*DSc+s]);
        uni = uni && (fabsf(as - (float)(s+1)*a0) <= 1e-4f*fabsf((float)(s+1)*a0) + 1e-6f);
    }
    float h[DSc];
    #pragma unroll
    for (int s = 0; s < DSc; ++s) h[s] = 0.f;
    float sdt = 0.f;
    if (uni) {
        for (int t = 0; t < Tc; ++t) {
            float v = bb;
            #pragma unroll
            for (int k = 0; k < 8; ++k) v += D8[t][k]*wr[k];
            float dt = (v > 15.f) ? v : __logf(1.f + __expf(v));
            float x  = g_xc[(size_t)(base+t)*DIc + d];
            sdt += dt;
            float u = dt*x;
            float e1 = __expf(dt*a0);
            float pk = 1.f;
            #pragma unroll
            for (int s = 0; s < DSc; ++s) { pk *= e1; h[s] = pk*h[s] + u*Bsh[t][s]; }
        }
    } else {
        for (int t = 0; t < Tc; ++t) {
            float v = bb;
            #pragma unroll
            for (int k = 0; k < 8; ++k) v += D8[t][k]*wr[k];
            float dt = (v > 15.f) ? v : __logf(1.f + __expf(v));
            float x  = g_xc[(size_t)(base+t)*DIc + d];
            sdt += dt;
            float u = dt*x;
            #pragma unroll
            for (int s = 0; s < DSc; ++s) {
                float as = -__expf(A_log[d*DSc+s]);
                h[s] = __expf(dt*as)*h[s] + u*Bsh[t][s];
            }
        }
    }
    size_t co = ((size_t)blk*DIc + d)*DSc;
    #pragma unroll
    for (int s = 0; s < DSc; ++s) g_ch[co+s] = h[s];
    g_sdt[(size_t)blk*DIc + d] = sdt;
}

// =====================================================================
// K4: sequential chunk combine
// =====================================================================
__global__ __launch_bounds__(256) void k_comb(const float* __restrict__ A_log)
{
    int id = blockIdx.x*256 + threadIdx.x;
    int b = id >> 12;
    int d = (id >> 4) & (DIc-1);
    int s = id & 15;
    float a = -__expf(A_log[d*DSc + s]);
    float H = 0.f;
    for (int ch = 0; ch < NCH; ++ch) {
        size_t off = ((size_t)(b*NCH+ch)*DIc + d)*DSc + s;
        g_hin[off] = H;
        float sdt = g_sdt[(size_t)(b*NCH+ch)*DIc + d];
        H = __expf(a*sdt)*H + g_ch[off];
    }
}

// =====================================================================
// K5: scan pass 2 (dt inline) — replay + fused +xc*D and *silu(z)
// =====================================================================
__global__ __launch_bounds__(256) void k_scan2(
    const float* __restrict__ A_log, const float* __restrict__ Dp,
    const float* __restrict__ dtw, const float* __restrict__ dtb)
{
    __shared__ float Bsh[Tc][DSc];
    __shared__ float Csh[Tc][DSc];
    __shared__ float D8 [Tc][8];
    int blk = blockIdx.x;
    int b = blk >> 7, ch = blk & (NCH-1);
    int base = b*Lc + ch*Tc;
    int tid = threadIdx.x, lane = tid & 31, wid = tid >> 5;
    for (int t = wid; t < Tc; t += 8) {
        if (lane < 32) {
            float v = g_dbc[(size_t)(base+t)*40 + lane];
            if (lane < 8)       D8[t][lane] = v;
            else if (lane < 24) Bsh[t][lane-8] = v;
            else                Csh[t][lane-24] = v;
        }
        if (lane < 8) {
            float w = g_dbc[(size_t)(base+t)*40 + 32 + lane];
            Csh[t][8 + lane] = w;
        }
    }
    __syncthreads();
    int d = tid;
    float wr[8];
    #pragma unroll
    for (int k = 0; k < 8; ++k) wr[k] = dtw[k*DIc + d];
    float bb = dtb[d];
    float a0 = -__expf(A_log[d*DSc]);
    bool uni = true;
    #pragma unroll
    for (int s = 1; s < DSc; ++s) {
        float as = -__expf(A_log[d*DSc+s]);
        uni = uni && (fabsf(as - (float)(s+1)*a0) <= 1e-4f*fabsf((float)(s+1)*a0) + 1e-6f);
    }
    float h[DSc];
    size_t ho = ((size_t)blk*DIc + d)*DSc;
    #pragma unroll
    for (int s = 0; s < DSc; ++s) h[s] = g_hin[ho+s];
    float dp = Dp[d];
    if (uni) {
        for (int t = 0; t < Tc; ++t) {
            float v = bb;
            #pragma unroll
            for (int k = 0; k < 8; ++k) v += D8[t][k]*wr[k];
            float dt = (v > 15.f) ? v : __logf(1.f + __expf(v));
            float x  = g_xc[(size_t)(base+t)*DIc + d];
            float u = dt*x;
            float e1 = __expf(dt*a0);
            float pk = 1.f, y = 0.f;
            #pragma unroll
            for (int s = 0; s < DSc; ++s) {
                pk *= e1;
                h[s] = pk*h[s] + u*Bsh[t][s];
                y += h[s]*Csh[t][s];
            }
            float zz = g_z[(size_t)(base+t)*DIc + d];
            float sil = zz / (1.f + __expf(-zz));
            g_y[(size_t)(base+t)*DIc + d] = (y + x*dp)*sil;
        }
    } else {
        for (int t = 0; t < Tc; ++t) {
            float v = bb;
            #pragma unroll
            for (int k = 0; k < 8; ++k) v += D8[t][k]*wr[k];
            float dt = (v > 15.f) ? v : __logf(1.f + __expf(v));
            float x  = g_xc[(size_t)(base+t)*DIc + d];
            float u = dt*x;
            float y = 0.f;
            #pragma unroll
            for (int s = 0; s < DSc; ++s) {
                float as = -__expf(A_log[d*DSc+s]);
                h[s] = __expf(dt*as)*h[s] + u*Bsh[t][s];
                y += h[s]*Csh[t][s];
            }
            float zz = g_z[(size_t)(base+t)*DIc + d];
            float sil = zz / (1.f + __expf(-zz));
            g_y[(size_t)(base+t)*DIc + d] = (y + x*dp)*sil;
        }
    }
}

// =====================================================================
// K6: out_proj (HMMA, M128 blk, N=128, K=256) + fused LayerNorm + scatter
// =====================================================================
__global__ __launch_bounds__(256) void k_out(
    const int* __restrict__ perm, const float* __restrict__ ln_w,
    const float* __restrict__ ln_b, float* __restrict__ out)
{
    extern __shared__ u16 sm[];
    u16 *Ah = sm, *Al = sm + 128*LDA, *Bh = sm + 2*128*LDA, *Bl = sm + 3*128*LDA;
    float* Cs = (float*)sm;             // overlays Ah/Al after compute
    const u32 Ah_u = smem_u32(Ah), Al_u = smem_u32(Al);
    const u32 Bh_u = smem_u32(Bh), Bl_u = smem_u32(Bl);
    const int tid = threadIdx.x, lane = tid & 31, wid = tid >> 5;
    const int m0 = blockIdx.x * 128;
    const int wm = wid >> 1, wn = wid & 1;

    float acc[2][8][4] = {};
    for (int kc = 0; kc < 2; ++kc) {
        int kk = kc*128;
        for (int i = tid; i < 128*64; i += 256) {
            int r = i >> 6, p = i & 63;
            float2 yv = *(const float2*)(g_y + (size_t)(m0+r)*DIc + kk + 2*p);
            u16 hx,lx,hy,ly;
            bfsplit(yv.x,hx,lx); bfsplit(yv.y,hy,ly);
            int base = r*LDA + 2*p;
            *(u32*)&Ah[base] = (u32)hx | ((u32)hy<<16);
            *(u32*)&Al[base] = (u32)lx | ((u32)ly<<16);
        }
        for (int i = tid; i < 128*64; i += 256) {
            int k = i >> 6, p = i & 63;
            *(u32*)&Bh[k*LDA + 2*p] = ((const u32*)g_wout_hi)[(kk+k)*64 + p];
            *(u32*)&Bl[k*LDA + 2*p] = ((const u32*)g_wout_lo)[(kk+k)*64 + p];
        }
        __syncthreads();

        #pragma unroll
        for (int pass = 0; pass < 3; ++pass) {
            u32 A_u = (pass == 2) ? Al_u : Ah_u;
            u32 B_u = (pass == 1) ? Bl_u : Bh_u;
            #pragma unroll
            for (int k0 = 0; k0 < 128; k0 += 16) {
                u32 a[2][4], b[8][2];
                #pragma unroll
                for (int mf = 0; mf < 2; ++mf)
                    LDSM4(a[mf], A_u + (u32)(((wm*32 + mf*16 + (lane & 15))*LDA
                                              + k0 + (lane >> 4)*8) * 2));
                #pragma unroll
                for (int nf2 = 0; nf2 < 4; ++nf2) {
                    u32 bb[4];
                    LDSM4T(bb, B_u + (u32)(((k0 + (lane & 15))*LDA
                                            + wn*64 + nf2*16 + (lane >> 4)*8) * 2));
                    b[2*nf2+0][0] = bb[0]; b[2*nf2+0][1] = bb[1];
                    b[2*nf2+1][0] = bb[2]; b[2*nf2+1][1] = bb[3];
                }
                #pragma unroll
                for (int mf = 0; mf < 2; ++mf)
                    #pragma unroll
                    for (int nf = 0; nf < 8; ++nf)
                        MMA(acc[mf][nf], a[mf], b[nf]);
            }
        }
        __syncthreads();
    }

    // stage accumulators to smem (stride 132 floats)
    #pragma unroll
    for (int mf = 0; mf < 2; ++mf) {
        int r0 = wm*32 + mf*16 + (lane >> 2);
        #pragma unroll
        for (int nf = 0; nf < 8; ++nf) {
            int ncol = wn*64 + nf*8 + (lane & 3)*2;
            *(float2*)&Cs[r0*132 + ncol]     = make_float2(acc[mf][nf][0], acc[mf][nf][1]);
            *(float2*)&Cs[(r0+8)*132 + ncol] = make_float2(acc[mf][nf][2], acc[mf][nf][3]);
        }
    }
    __syncthreads();

    // LayerNorm + inverse-perm scatter: each warp handles 16 rows
    for (int rr = 0; rr < 16; ++rr) {
        int row = wid*16 + rr;
        float4 v4 = *(float4*)&Cs[row*132 + lane*4];
        float v[4] = {v4.x, v4.y, v4.z, v4.w};
        float sum = 0.f, ssq = 0.f;
        #pragma unroll
        for (int j = 0; j < 4; ++j) { sum += v[j]; ssq += v[j]*v[j]; }
        #pragma unroll
        for (int o = 16; o > 0; o >>= 1) {
            sum += __shfl_xor_sync(0xffffffffu, sum, o);
            ssq += __shfl_xor_sync(0xffffffffu, ssq, o);
        }
        float mu  = sum * (1.f/Dc);
        float var = ssq * (1.f/Dc) - mu*mu;
        float rs  = rsqrtf(var + EPSc);
        int m = m0 + row;
        int dst = (m & ~(Lc-1)) + perm[m];
        int c = lane*4;
        float4 o4;
        o4.x = (v[0]-mu)*rs*ln_w[c+0] + ln_b[c+0];
        o4.y = (v[1]-mu)*rs*ln_w[c+1] + ln_b[c+1];
        o4.z = (v[2]-mu)*rs*ln_w[c+2] + ln_b[c+2];
        o4.w = (v[3]-mu)*rs*ln_w[c+3] + ln_b[c+3];
        *(float4*)(out + (size_t)dst*Dc + c) = o4;
    }
}

// =====================================================================
extern "C" void kernel_launch(void* const* d_in, const int* in_sizes, int n_in,
                              void* d_out, int out_size)
{
    const float* feats      = (const float*)d_in[0];
    const float* pos_w      = (const float*)d_in[1];
    const float* pos_b      = (const float*)d_in[2];
    const float* rms_w      = (const float*)d_in[3];
    const float* in_proj_w  = (const float*)d_in[4];
    const float* conv_w     = (const float*)d_in[5];
    const float* conv_b     = (const float*)d_in[6];
    const float* x_proj_w   = (const float*)d_in[7];
    const float* dt_proj_w  = (const float*)d_in[8];
    const float* dt_proj_b  = (const float*)d_in[9];
    const float* A_log      = (const float*)d_in[10];
    const float* D_param    = (const float*)d_in[11];
    const float* out_proj_w = (const float*)d_in[12];
    const float* ln_w       = (const float*)d_in[13];
    const float* ln_b       = (const float*)d_in[14];
    const int*   coords     = (const int*)  d_in[15];
    const int*   perm       = (const int*)  d_in[16];
    float* out = (float*)d_out;

    const int SM_IN  = 4*128*LDA*2;                       // 139264
    const int SM_XP  = 2*128*LDA*2 + 2*128*LDB2*2;        // 106496
    const int SM_OUT = 4*128*LDA*2;                       // 139264
    cudaFuncSetAttribute(k_in,  cudaFuncAttributeMaxDynamicSharedMemorySize, SM_IN);
    cudaFuncSetAttribute(k_xp,  cudaFuncAttributeMaxDynamicSharedMemorySize, SM_XP);
    cudaFuncSetAttribute(k_out, cudaFuncAttributeMaxDynamicSharedMemorySize, SM_OUT);

    k_prep <<<(128*512 + 256*128 + 256*64)/256, 256>>>(in_proj_w, out_proj_w, x_proj_w);
    k_in   <<<Nc/128, 256, SM_IN>>>(feats, coords, pos_w, pos_b, rms_w, perm);
    k_xp   <<<Nc/128, 256, SM_XP>>>(conv_w, conv_b);
    k_scan1<<<Bc*NCH, 256>>>(A_log, dt_proj_w, dt_proj_b);
    k_comb <<<(Bc*DIc*DSc)/256, 256>>>(A_log);
    k_scan2<<<Bc*NCH, 256>>>(A_log, D_param, dt_proj_w, dt_proj_b);
    k_out  <<<Nc/128, 256, SM_OUT>>>(perm, ln_w, ln_b, out);
}